// round 1
// baseline (speedup 1.0000x reference)
#include <cuda_runtime.h>
#include <cstdint>

// Problem constants (fixed by the benchmark's setup_inputs)
#define BB 64
#define LL 4096
#define EE 64
#define SS 45          // sample_k == u == min(5*ceil(ln 4096), 4096) = 45
#define NT 8           // cumsum tiles per sequence
#define TILE 512       // LL / NT
#define NKT 4          // k-tiles for the attn@V partial accumulation

#define NEG_INF (-3.402823466e+38f)

// ---------------- scratch (static device globals; no runtime allocation) ----
__device__ float d_M[BB * LL];                         // 1 MB: sparsity scores
__device__ int   d_Mtop[BB * 64];                      // top-45 indices per batch
__device__ float d_scores[(size_t)BB * 48 * LL];       // 50 MB: scores -> attn (in place)
__device__ float d_updp[NKT * BB * SS * EE];           // 12 MB: partial upd per k-tile
__device__ float d_tsum[BB * NT * EE];                 // cumsum tile sums

// ============================================================================
// Kernel A: M[b,l] = max_s q.k_idx  -  (sum_s q.k_idx)/L
// One thread per (b,l). q row held in registers; 45 gathered key rows streamed
// (256B each, L2-resident since keys[b] = 1MB).
// ============================================================================
__global__ __launch_bounds__(128) void kA(const float* __restrict__ q,
                                          const float* __restrict__ k,
                                          const int*   __restrict__ idx) {
    int gid = blockIdx.x * blockDim.x + threadIdx.x;   // b*LL + l
    if (gid >= BB * LL) return;
    int b = gid >> 12;
    int l = gid & (LL - 1);

    const float4* qr = reinterpret_cast<const float4*>(q + (size_t)gid * EE);
    float4 qv[16];
#pragma unroll
    for (int i = 0; i < 16; i++) qv[i] = qr[i];

    const int* il = idx + (size_t)l * SS;
    const float* kb = k + (size_t)b * LL * EE;

    float mx = NEG_INF;
    float sm = 0.0f;
    for (int s = 0; s < SS; s++) {
        int j = il[s];
        const float4* kr = reinterpret_cast<const float4*>(kb + (size_t)j * EE);
        float d = 0.0f;
#pragma unroll
        for (int i = 0; i < 16; i++) {
            float4 kv = kr[i];
            d = fmaf(qv[i].x, kv.x, d);
            d = fmaf(qv[i].y, kv.y, d);
            d = fmaf(qv[i].z, kv.z, d);
            d = fmaf(qv[i].w, kv.w, d);
        }
        mx = fmaxf(mx, d);
        sm += d;
    }
    d_M[gid] = mx - sm * (1.0f / (float)LL);
}

// ============================================================================
// Kernel B: per-batch top-45 of M (iterative argmax; tie -> lower index, matching
// jax.lax.top_k). One block per batch.
// ============================================================================
__global__ __launch_bounds__(1024) void kB() {
    __shared__ float sv[LL];
    __shared__ float wmax[32];
    __shared__ int   widx[32];
    int b = blockIdx.x, t = threadIdx.x;

    for (int i = t; i < LL; i += 1024) sv[i] = d_M[b * LL + i];
    __syncthreads();

    for (int it = 0; it < SS; it++) {
        float best = NEG_INF;
        int   bi   = LL;   // sentinel larger than any index
        for (int i = t; i < LL; i += 1024) {
            float vv = sv[i];
            if (vv > best) { best = vv; bi = i; }
        }
        // warp reduce (value desc, index asc on ties)
#pragma unroll
        for (int o = 16; o > 0; o >>= 1) {
            float ov = __shfl_down_sync(0xffffffffu, best, o);
            int   oi = __shfl_down_sync(0xffffffffu, bi, o);
            if (ov > best || (ov == best && oi < bi)) { best = ov; bi = oi; }
        }
        if ((t & 31) == 0) { wmax[t >> 5] = best; widx[t >> 5] = bi; }
        __syncthreads();
        if (t == 0) {
            float bb = wmax[0]; int bbi = widx[0];
#pragma unroll
            for (int w = 1; w < 32; w++) {
                if (wmax[w] > bb || (wmax[w] == bb && widx[w] < bbi)) {
                    bb = wmax[w]; bbi = widx[w];
                }
            }
            d_Mtop[b * 64 + it] = bbi;
            sv[bbi] = NEG_INF;
        }
        __syncthreads();
    }
}

// ============================================================================
// Kernel C1: scores[b,u,k] = (q[b, Mtop[b,u]] . keys[b,k]) * scale
// grid (32 k-tiles, B), 128 threads. Qr tile in shared; each thread owns one
// key row in registers and produces 45 scores.
// ============================================================================
__global__ __launch_bounds__(128) void kC1(const float* __restrict__ q,
                                           const float* __restrict__ k) {
    __shared__ float qs[SS * EE];
    int b = blockIdx.y, t = threadIdx.x;

    for (int i = t; i < SS * EE; i += 128) {
        int u = i >> 6, e = i & 63;
        int row = d_Mtop[b * 64 + u];
        qs[i] = q[((size_t)b * LL + row) * EE + e];
    }
    __syncthreads();

    int kk = blockIdx.x * 128 + t;
    const float4* kr = reinterpret_cast<const float4*>(k + ((size_t)b * LL + kk) * EE);
    float4 kv[16];
#pragma unroll
    for (int i = 0; i < 16; i++) kv[i] = kr[i];

    const float scale = 0.125f;  // 1/sqrt(64)
    float* srow = d_scores + (size_t)b * SS * LL + kk;
    const float4* qs4 = reinterpret_cast<const float4*>(qs);
#pragma unroll 1
    for (int u = 0; u < SS; u++) {
        float d = 0.0f;
#pragma unroll
        for (int i = 0; i < 16; i++) {
            float4 qv = qs4[u * 16 + i];
            d = fmaf(qv.x, kv[i].x, d);
            d = fmaf(qv.y, kv[i].y, d);
            d = fmaf(qv.z, kv[i].z, d);
            d = fmaf(qv.w, kv[i].w, d);
        }
        srow[(size_t)u * LL] = d * scale;
    }
}

// ============================================================================
// Kernel C2: in-place softmax over k for each (b,u) row. One block per row.
// ============================================================================
__global__ __launch_bounds__(256) void kC2() {
    __shared__ float red[256];
    int t = threadIdx.x;
    float* row = d_scores + (size_t)blockIdx.x * LL;

    float vreg[16];
    float mx = NEG_INF;
#pragma unroll
    for (int i = 0; i < 16; i++) {
        vreg[i] = row[t + i * 256];
        mx = fmaxf(mx, vreg[i]);
    }
    red[t] = mx;
    __syncthreads();
#pragma unroll
    for (int o = 128; o > 0; o >>= 1) {
        if (t < o) red[t] = fmaxf(red[t], red[t + o]);
        __syncthreads();
    }
    float m = red[0];
    __syncthreads();

    float s = 0.0f;
#pragma unroll
    for (int i = 0; i < 16; i++) {
        vreg[i] = __expf(vreg[i] - m);
        s += vreg[i];
    }
    red[t] = s;
    __syncthreads();
#pragma unroll
    for (int o = 128; o > 0; o >>= 1) {
        if (t < o) red[t] += red[t + o];
        __syncthreads();
    }
    float inv = 1.0f / red[0];
#pragma unroll
    for (int i = 0; i < 16; i++) row[t + i * 256] = vreg[i] * inv;
}

// ============================================================================
// Kernel C3: partial upd[kt][b,u,e] = sum_{k in ktile} attn[b,u,k] * v[b,k,e]
// grid (B, NKT), 256 threads: e = t&63, kg = t>>6 covers a contiguous 256-k
// sub-range; attn read as float4 (broadcast within warp), deterministic
// shared-memory reduction across the 4 kg groups.
// ============================================================================
__global__ __launch_bounds__(256) void kC3(const float* __restrict__ v) {
    __shared__ float sred[SS * EE];
    int b = blockIdx.x;
    int t = threadIdx.x;
    int e = t & 63, kg = t >> 6;
    int kbase = blockIdx.y * (LL / NKT) + kg * 256;

    const float* attn = d_scores + (size_t)b * SS * LL;
    const float* vb = v + (size_t)b * LL * EE;

    float acc[SS];
#pragma unroll
    for (int u = 0; u < SS; u++) acc[u] = 0.0f;

    for (int kb2 = 0; kb2 < 256; kb2 += 4) {
        int k0 = kbase + kb2;
        float vv0 = vb[(size_t)(k0 + 0) * EE + e];
        float vv1 = vb[(size_t)(k0 + 1) * EE + e];
        float vv2 = vb[(size_t)(k0 + 2) * EE + e];
        float vv3 = vb[(size_t)(k0 + 3) * EE + e];
#pragma unroll
        for (int u = 0; u < SS; u++) {
            float4 a4 = *reinterpret_cast<const float4*>(&attn[(size_t)u * LL + k0]);
            float r = acc[u];
            r = fmaf(a4.x, vv0, r);
            r = fmaf(a4.y, vv1, r);
            r = fmaf(a4.z, vv2, r);
            r = fmaf(a4.w, vv3, r);
            acc[u] = r;
        }
    }

    // deterministic cross-kg reduction
    if (kg == 0) {
#pragma unroll
        for (int u = 0; u < SS; u++) sred[u * 64 + e] = acc[u];
    }
    __syncthreads();
    for (int r = 1; r < 4; r++) {
        if (kg == r) {
#pragma unroll
            for (int u = 0; u < SS; u++) sred[u * 64 + e] += acc[u];
        }
        __syncthreads();
    }
    float* outp = d_updp + (((size_t)blockIdx.y * BB + b) * SS) * EE;
    for (int i = t; i < SS * EE; i += 256) outp[i] = sred[i];
}

// ============================================================================
// Kernel D1: per-tile column sums of values (for the cumsum scan).
// grid (B, NT), 256 threads: e = t&63, g = t>>6 handles 128 rows.
// ============================================================================
__global__ __launch_bounds__(256) void kD1(const float* __restrict__ v) {
    __shared__ float sred[4 * EE];
    int b = blockIdx.x, tile = blockIdx.y, t = threadIdx.x;
    int e = t & 63, g = t >> 6;
    const float* vp = v + ((size_t)b * LL + tile * TILE + g * (TILE / 4)) * EE + e;

    float s = 0.0f;
#pragma unroll 8
    for (int i = 0; i < TILE / 4; i++) s += vp[(size_t)i * EE];
    sred[g * EE + e] = s;
    __syncthreads();
    if (g == 0) {
        float tot = sred[e] + sred[EE + e] + sred[2 * EE + e] + sred[3 * EE + e];
        d_tsum[((size_t)b * NT + tile) * EE + e] = tot;
    }
}

// ============================================================================
// Kernel D3: within-tile inclusive scan + previous-tile offsets -> out.
// grid (B, NT), 64 threads (one per e-column), serial over TILE rows,
// unrolled by 8 for load MLP.
// ============================================================================
__global__ __launch_bounds__(64) void kD3(const float* __restrict__ v,
                                          float* __restrict__ out) {
    int b = blockIdx.x, tile = blockIdx.y, e = threadIdx.x;

    float acc = 0.0f;
    for (int tt = 0; tt < tile; tt++) acc += d_tsum[((size_t)b * NT + tt) * EE + e];

    const float* vp = v + ((size_t)b * LL + tile * TILE) * EE + e;
    float* op = out + ((size_t)b * LL + tile * TILE) * EE + e;

    for (int i = 0; i < TILE; i += 8) {
        float x[8];
#pragma unroll
        for (int j = 0; j < 8; j++) x[j] = vp[(size_t)(i + j) * EE];
#pragma unroll
        for (int j = 0; j < 8; j++) { acc += x[j]; x[j] = acc; }
#pragma unroll
        for (int j = 0; j < 8; j++) op[(size_t)(i + j) * EE] = x[j];
    }
}

// ============================================================================
// Kernel E: sum the NKT upd partials and scatter into out at the top-k rows.
// grid B*SS blocks of 64 threads. Runs after D3 (overwrites scanned rows).
// ============================================================================
__global__ __launch_bounds__(64) void kE(float* __restrict__ out) {
    int bu = blockIdx.x;
    int b = bu / SS, u = bu % SS;
    int e = threadIdx.x;
    int row = d_Mtop[b * 64 + u];

    float s = 0.0f;
#pragma unroll
    for (int kt = 0; kt < NKT; kt++)
        s += d_updp[(((size_t)kt * BB + b) * SS + u) * EE + e];

    out[((size_t)b * LL + row) * EE + e] = s;
}

// ============================================================================
extern "C" void kernel_launch(void* const* d_in, const int* in_sizes, int n_in,
                              void* d_out, int out_size) {
    const float* q   = (const float*)d_in[0];
    const float* k   = (const float*)d_in[1];
    const float* v   = (const float*)d_in[2];
    const int*   idx = (const int*)d_in[3];
    float* out = (float*)d_out;

    kA<<<(BB * LL) / 128, 128>>>(q, k, idx);
    kB<<<BB, 1024>>>();
    kC1<<<dim3(LL / 128, BB), 128>>>(q, k);
    kC2<<<BB * SS, 256>>>();
    kC3<<<dim3(BB, NKT), 256>>>(v);
    kD1<<<dim3(BB, NT), 256>>>(v);
    kD3<<<dim3(BB, NT), 64>>>(v, out);
    kE<<<BB * SS, 64>>>(out);
}

// round 2
// speedup vs baseline: 1.3359x; 1.3359x over previous
#include <cuda_runtime.h>
#include <cstdint>

// Problem constants (fixed by the benchmark's setup_inputs)
#define BB 64
#define LL 4096
#define EE 64
#define SS 45          // sample_k == u == 45
#define NT 32          // cumsum tiles per sequence
#define TILE 128       // LL / NT
#define NKT 4          // k-tiles for attn@V partials

#define NCH 8          // key chunks for the M-score phase
#define CROWS 512      // rows per chunk (LL / NCH)
#define KPAD 68        // padded smem row stride (floats) -> breaks bank alignment
#define EMAX 28672     // entry capacity per chunk (mean 23040, sd ~142)

#define NEG_INF (-3.402823466e+38f)

// ---------------- scratch (static device globals) ---------------------------
__device__ float d_M[BB * LL];
__device__ int   d_Mtop[BB * 64];
__device__ float d_scores[(size_t)BB * 48 * LL];       // 50 MB
__device__ float d_updp[NKT * BB * SS * EE];
__device__ float d_tsum[BB * NT * EE];

__device__ int            d_cnt[NCH * LL];             // samples of l in chunk c
__device__ int            d_base[NCH * LL];            // CSR base (excl. prefix)
__device__ unsigned short d_ent[NCH][EMAX];            // local row ids (0..511)
__device__ float          d_pmax[(size_t)NCH * BB * LL];
__device__ float          d_psum[(size_t)NCH * BB * LL];

// ============================================================================
// P1: per-(chunk,l) sample counts. Batch-independent.
// ============================================================================
__global__ __launch_bounds__(256) void kP1(const int* __restrict__ idx) {
    int l = blockIdx.x * 256 + threadIdx.x;
    if (l >= LL) return;
    const int* il = idx + (size_t)l * SS;
    unsigned long long pk = 0;                 // 8 packed 8-bit counters
#pragma unroll
    for (int s = 0; s < SS; s++) {
        int c = il[s] >> 9;
        pk += 1ull << (c * 8);
    }
#pragma unroll
    for (int c = 0; c < NCH; c++)
        d_cnt[c * LL + l] = (int)((pk >> (c * 8)) & 255ull);
}

// ============================================================================
// P2: per-chunk exclusive prefix over l (Hillis-Steele on 1024 thread sums).
// ============================================================================
__global__ __launch_bounds__(1024) void kP2() {
    __shared__ int sh[1024];
    int c = blockIdx.x, t = threadIdx.x;
    int v0 = d_cnt[c * LL + t * 4 + 0];
    int v1 = d_cnt[c * LL + t * 4 + 1];
    int v2 = d_cnt[c * LL + t * 4 + 2];
    int v3 = d_cnt[c * LL + t * 4 + 3];
    int ts = v0 + v1 + v2 + v3;
    sh[t] = ts;
    __syncthreads();
    for (int off = 1; off < 1024; off <<= 1) {
        int x = (t >= off) ? sh[t - off] : 0;
        __syncthreads();
        sh[t] += x;
        __syncthreads();
    }
    int excl = sh[t] - ts;
    d_base[c * LL + t * 4 + 0] = excl;
    d_base[c * LL + t * 4 + 1] = excl + v0;
    d_base[c * LL + t * 4 + 2] = excl + v0 + v1;
    d_base[c * LL + t * 4 + 3] = excl + v0 + v1 + v2;
}

// ============================================================================
// P3: scatter entries (local row ids) into the per-chunk CSR lists.
// ============================================================================
__global__ __launch_bounds__(256) void kP3(const int* __restrict__ idx) {
    int l = blockIdx.x * 256 + threadIdx.x;
    if (l >= LL) return;
    int off[NCH];
#pragma unroll
    for (int c = 0; c < NCH; c++) off[c] = d_base[c * LL + l];
    const int* il = idx + (size_t)l * SS;
#pragma unroll
    for (int s = 0; s < SS; s++) {
        int j = il[s];
        int c = j >> 9;
        d_ent[c][off[c]++] = (unsigned short)(j & 511);
    }
}

// ============================================================================
// kA2: per-(chunk,b) partial M stats. Key chunk staged in smem (padded).
// 8-lane groups: lane lg covers e=[8*lg, 8*lg+8). Uniform inner bound keeps
// the warp convergent for the shfl reductions.
// grid (NCH, BB, 2), 512 threads, 139264B dynamic smem.
// ============================================================================
extern __shared__ float ks[];
__global__ __launch_bounds__(512) void kA2(const float* __restrict__ q,
                                           const float* __restrict__ k) {
    int c = blockIdx.x, b = blockIdx.y, z = blockIdx.z;
    int t = threadIdx.x;

    const float* kb = k + ((size_t)b * LL + c * CROWS) * EE;
    for (int i = t; i < CROWS * EE; i += 512) {
        int r = i >> 6, e = i & 63;
        ks[r * KPAD + e] = kb[i];
    }
    __syncthreads();

    int g = t >> 3, lg = t & 7;                     // 64 groups of 8 lanes
    float* pmax = d_pmax + ((size_t)c * BB + b) * LL;
    float* psum = d_psum + ((size_t)c * BB + b) * LL;

    int lend = z * 2048 + 2048;
    for (int l = z * 2048 + g; l < lend; l += 64) {
        int cnt  = d_cnt[c * LL + l];
        int base = d_base[c * LL + l];
        int mc = cnt;                               // warp-max count (uniform)
        mc = max(mc, __shfl_xor_sync(0xffffffffu, mc, 8));
        mc = max(mc, __shfl_xor_sync(0xffffffffu, mc, 16));

        float mx = NEG_INF, sm = 0.0f;
        if (mc > 0) {
            float4 qa = make_float4(0.f, 0.f, 0.f, 0.f), qb4 = qa;
            if (cnt > 0) {
                const float4* qp =
                    (const float4*)(q + ((size_t)b * LL + l) * EE + lg * 8);
                qa  = __ldcs(qp);
                qb4 = __ldcs(qp + 1);
            }
            for (int e = 0; e < mc; e++) {
                int ei = base + ((e < cnt) ? e : 0);
                int jr = d_ent[c][ei];
                const float4* kp = (const float4*)&ks[jr * KPAD + lg * 8];
                float4 k0 = kp[0], k1 = kp[1];
                float p = qa.x * k0.x;
                p = fmaf(qa.y, k0.y, p);
                p = fmaf(qa.z, k0.z, p);
                p = fmaf(qa.w, k0.w, p);
                p = fmaf(qb4.x, k1.x, p);
                p = fmaf(qb4.y, k1.y, p);
                p = fmaf(qb4.z, k1.z, p);
                p = fmaf(qb4.w, k1.w, p);
                p += __shfl_xor_sync(0xffffffffu, p, 1);
                p += __shfl_xor_sync(0xffffffffu, p, 2);
                p += __shfl_xor_sync(0xffffffffu, p, 4);
                if (e < cnt) { mx = fmaxf(mx, p); sm += p; }
            }
        }
        if (lg == 0) { pmax[l] = mx; psum[l] = sm; }
    }
}

// ============================================================================
// kA3: combine chunk partials -> M[b,l].
// ============================================================================
__global__ __launch_bounds__(256) void kA3() {
    int gid = blockIdx.x * 256 + threadIdx.x;      // b*LL + l
    int b = gid >> 12, l = gid & (LL - 1);
    float mx = NEG_INF, sm = 0.0f;
#pragma unroll
    for (int c = 0; c < NCH; c++) {
        mx = fmaxf(mx, d_pmax[((size_t)c * BB + b) * LL + l]);
        sm += d_psum[((size_t)c * BB + b) * LL + l];
    }
    d_M[gid] = mx - sm * (1.0f / (float)LL);
}

// ============================================================================
// kB: per-batch top-45 of M (iterative argmax; tie -> lower index).
// ============================================================================
__global__ __launch_bounds__(1024) void kB() {
    __shared__ float sv[LL];
    __shared__ float wmax[32];
    __shared__ int   widx[32];
    int b = blockIdx.x, t = threadIdx.x;

    for (int i = t; i < LL; i += 1024) sv[i] = d_M[b * LL + i];
    __syncthreads();

    for (int it = 0; it < SS; it++) {
        float best = NEG_INF;
        int   bi   = LL;
        for (int i = t; i < LL; i += 1024) {
            float vv = sv[i];
            if (vv > best) { best = vv; bi = i; }
        }
#pragma unroll
        for (int o = 16; o > 0; o >>= 1) {
            float ov = __shfl_down_sync(0xffffffffu, best, o);
            int   oi = __shfl_down_sync(0xffffffffu, bi, o);
            if (ov > best || (ov == best && oi < bi)) { best = ov; bi = oi; }
        }
        if ((t & 31) == 0) { wmax[t >> 5] = best; widx[t >> 5] = bi; }
        __syncthreads();
        if (t == 0) {
            float bb2 = wmax[0]; int bbi = widx[0];
#pragma unroll
            for (int w = 1; w < 32; w++) {
                if (wmax[w] > bb2 || (wmax[w] == bb2 && widx[w] < bbi)) {
                    bb2 = wmax[w]; bbi = widx[w];
                }
            }
            d_Mtop[b * 64 + it] = bbi;
            sv[bbi] = NEG_INF;
        }
        __syncthreads();
    }
}

// ============================================================================
// kC1: scores[b,u,k] = (q[b, Mtop[b,u]] . keys[b,k]) * scale
// ============================================================================
__global__ __launch_bounds__(128) void kC1(const float* __restrict__ q,
                                           const float* __restrict__ k) {
    __shared__ float qs[SS * EE];
    int b = blockIdx.y, t = threadIdx.x;

    for (int i = t; i < SS * EE; i += 128) {
        int u = i >> 6, e = i & 63;
        int row = d_Mtop[b * 64 + u];
        qs[i] = q[((size_t)b * LL + row) * EE + e];
    }
    __syncthreads();

    int kk = blockIdx.x * 128 + t;
    const float4* kr = reinterpret_cast<const float4*>(k + ((size_t)b * LL + kk) * EE);
    float4 kv[16];
#pragma unroll
    for (int i = 0; i < 16; i++) kv[i] = kr[i];

    const float scale = 0.125f;
    float* srow = d_scores + (size_t)b * SS * LL + kk;
    const float4* qs4 = reinterpret_cast<const float4*>(qs);
#pragma unroll 1
    for (int u = 0; u < SS; u++) {
        float d = 0.0f;
#pragma unroll
        for (int i = 0; i < 16; i++) {
            float4 qv = qs4[u * 16 + i];
            d = fmaf(qv.x, kv[i].x, d);
            d = fmaf(qv.y, kv[i].y, d);
            d = fmaf(qv.z, kv[i].z, d);
            d = fmaf(qv.w, kv[i].w, d);
        }
        srow[(size_t)u * LL] = d * scale;
    }
}

// ============================================================================
// kC2: in-place softmax over k for each (b,u) row.
// ============================================================================
__global__ __launch_bounds__(256) void kC2() {
    __shared__ float red[256];
    int t = threadIdx.x;
    float* row = d_scores + (size_t)blockIdx.x * LL;

    float vreg[16];
    float mx = NEG_INF;
#pragma unroll
    for (int i = 0; i < 16; i++) {
        vreg[i] = row[t + i * 256];
        mx = fmaxf(mx, vreg[i]);
    }
    red[t] = mx;
    __syncthreads();
#pragma unroll
    for (int o = 128; o > 0; o >>= 1) {
        if (t < o) red[t] = fmaxf(red[t], red[t + o]);
        __syncthreads();
    }
    float m = red[0];
    __syncthreads();

    float s = 0.0f;
#pragma unroll
    for (int i = 0; i < 16; i++) {
        vreg[i] = __expf(vreg[i] - m);
        s += vreg[i];
    }
    red[t] = s;
    __syncthreads();
#pragma unroll
    for (int o = 128; o > 0; o >>= 1) {
        if (t < o) red[t] += red[t + o];
        __syncthreads();
    }
    float inv = 1.0f / red[0];
#pragma unroll
    for (int i = 0; i < 16; i++) row[t + i * 256] = vreg[i] * inv;
}

// ============================================================================
// kC3: partial upd[kt][b,u,e] over a contiguous k-range; deterministic smem
// reduction across the 4 kg groups.
// ============================================================================
__global__ __launch_bounds__(256) void kC3(const float* __restrict__ v) {
    __shared__ float sred[SS * EE];
    int b = blockIdx.x;
    int t = threadIdx.x;
    int e = t & 63, kg = t >> 6;
    int kbase = blockIdx.y * (LL / NKT) + kg * 256;

    const float* attn = d_scores + (size_t)b * SS * LL;
    const float* vb = v + (size_t)b * LL * EE;

    float acc[SS];
#pragma unroll
    for (int u = 0; u < SS; u++) acc[u] = 0.0f;

    for (int kb2 = 0; kb2 < 256; kb2 += 4) {
        int k0 = kbase + kb2;
        float vv0 = vb[(size_t)(k0 + 0) * EE + e];
        float vv1 = vb[(size_t)(k0 + 1) * EE + e];
        float vv2 = vb[(size_t)(k0 + 2) * EE + e];
        float vv3 = vb[(size_t)(k0 + 3) * EE + e];
#pragma unroll
        for (int u = 0; u < SS; u++) {
            float4 a4 = *reinterpret_cast<const float4*>(&attn[(size_t)u * LL + k0]);
            float r = acc[u];
            r = fmaf(a4.x, vv0, r);
            r = fmaf(a4.y, vv1, r);
            r = fmaf(a4.z, vv2, r);
            r = fmaf(a4.w, vv3, r);
            acc[u] = r;
        }
    }

    if (kg == 0) {
#pragma unroll
        for (int u = 0; u < SS; u++) sred[u * 64 + e] = acc[u];
    }
    __syncthreads();
    for (int r = 1; r < 4; r++) {
        if (kg == r) {
#pragma unroll
            for (int u = 0; u < SS; u++) sred[u * 64 + e] += acc[u];
        }
        __syncthreads();
    }
    float* outp = d_updp + (((size_t)blockIdx.y * BB + b) * SS) * EE;
    for (int i = t; i < SS * EE; i += 256) outp[i] = sred[i];
}

// ============================================================================
// kD1: per-tile column sums of values (scan phase 1).
// ============================================================================
__global__ __launch_bounds__(256) void kD1(const float* __restrict__ v) {
    __shared__ float sred[4 * EE];
    int b = blockIdx.x, tile = blockIdx.y, t = threadIdx.x;
    int e = t & 63, g = t >> 6;
    const float* vp = v + ((size_t)b * LL + tile * TILE + g * (TILE / 4)) * EE + e;

    float s = 0.0f;
#pragma unroll 8
    for (int i = 0; i < TILE / 4; i++) s += vp[(size_t)i * EE];
    sred[g * EE + e] = s;
    __syncthreads();
    if (g == 0) {
        float tot = sred[e] + sred[EE + e] + sred[2 * EE + e] + sred[3 * EE + e];
        d_tsum[((size_t)b * NT + tile) * EE + e] = tot;
    }
}

// ============================================================================
// kD3: within-tile inclusive scan + previous-tile offsets -> out.
// ============================================================================
__global__ __launch_bounds__(64) void kD3(const float* __restrict__ v,
                                          float* __restrict__ out) {
    int b = blockIdx.x, tile = blockIdx.y, e = threadIdx.x;

    float acc = 0.0f;
    for (int tt = 0; tt < tile; tt++) acc += d_tsum[((size_t)b * NT + tt) * EE + e];

    const float* vp = v + ((size_t)b * LL + tile * TILE) * EE + e;
    float* op = out + ((size_t)b * LL + tile * TILE) * EE + e;

    for (int i = 0; i < TILE; i += 8) {
        float x[8];
#pragma unroll
        for (int j = 0; j < 8; j++) x[j] = vp[(size_t)(i + j) * EE];
#pragma unroll
        for (int j = 0; j < 8; j++) { acc += x[j]; x[j] = acc; }
#pragma unroll
        for (int j = 0; j < 8; j++) op[(size_t)(i + j) * EE] = x[j];
    }
}

// ============================================================================
// kE: sum the NKT upd partials and scatter into out at the top-k rows.
// ============================================================================
__global__ __launch_bounds__(64) void kE(float* __restrict__ out) {
    int bu = blockIdx.x;
    int b = bu / SS, u = bu % SS;
    int e = threadIdx.x;
    int row = d_Mtop[b * 64 + u];

    float s = 0.0f;
#pragma unroll
    for (int kt = 0; kt < NKT; kt++)
        s += d_updp[(((size_t)kt * BB + b) * SS + u) * EE + e];

    out[((size_t)b * LL + row) * EE + e] = s;
}

// ============================================================================
extern "C" void kernel_launch(void* const* d_in, const int* in_sizes, int n_in,
                              void* d_out, int out_size) {
    const float* q   = (const float*)d_in[0];
    const float* k   = (const float*)d_in[1];
    const float* v   = (const float*)d_in[2];
    const int*   idx = (const int*)d_in[3];
    float* out = (float*)d_out;

    const int smemA2 = CROWS * KPAD * 4;   // 139264 bytes
    cudaFuncSetAttribute(kA2, cudaFuncAttributeMaxDynamicSharedMemorySize, smemA2);

    kP1<<<LL / 256, 256>>>(idx);
    kP2<<<NCH, 1024>>>();
    kP3<<<LL / 256, 256>>>(idx);
    kA2<<<dim3(NCH, BB, 2), 512, smemA2>>>(q, k);
    kA3<<<(BB * LL) / 256, 256>>>();
    kB<<<BB, 1024>>>();
    kC1<<<dim3(LL / 128, BB), 128>>>(q, k);
    kC2<<<BB * SS, 256>>>();
    kC3<<<dim3(BB, NKT), 256>>>(v);
    kD1<<<dim3(BB, NT), 256>>>(v);
    kD3<<<dim3(BB, NT), 64>>>(v, out);
    kE<<<BB * SS, 64>>>(out);
}